// round 14
// baseline (speedup 1.0000x reference)
#include <cuda_runtime.h>
#include <math.h>
#include <stdint.h>

#define D_MODEL 1024
#define NH 16
#define DH 64
#define BATCH 4
#define SEQ 1024
#define MROWS (BATCH*SEQ)        // 4096
#define QK_COUNT 4194304.0f
#define EPS 1e-6f
#define LOG2E 1.4426950408889634f

typedef unsigned long long ull;

// ---------------- scratch ---------------------------------------------------
__device__ float g_qkv[MROWS * 3 * D_MODEL];   // 48 MB
__device__ float g_xt[D_MODEL * MROWS];        // 16 MB  (x^T)
__device__ float g_zt[D_MODEL * MROWS];        // 16 MB  (z^T, written by flash)
__device__ float g_sumsq[2];
__device__ float g_inv[2];

// ---------------- tiny kernels ----------------------------------------------
__global__ void finalize_kernel(const float* __restrict__ ss, float* __restrict__ inv) {
    if (threadIdx.x < 2) {
        float rms = sqrtf(ss[threadIdx.x] / QK_COUNT);
        inv[threadIdx.x] = 1.0f / (rms + EPS);
    }
}

// ---------------- transpose (+ zero sumsq): out[C][R] = in[R][C] ---------------
__global__ __launch_bounds__(256)
void transpose_kernel(const float* __restrict__ in, float* __restrict__ out,
                      int R, int C, float* ss)
{
    __shared__ float tile[32][33];
    if (blockIdx.x == 0 && blockIdx.y == 0 && threadIdx.x < 2) ss[threadIdx.x] = 0.0f;
    const int tx = threadIdx.x & 31;
    const int ty = threadIdx.x >> 5;
    const int bx = blockIdx.x * 32;
    const int by = blockIdx.y * 32;
#pragma unroll
    for (int j = 0; j < 32; j += 8)
        tile[ty + j][tx] = in[(size_t)(by + ty + j) * C + bx + tx];
    __syncthreads();
#pragma unroll
    for (int j = 0; j < 32; j += 8)
        out[(size_t)(bx + ty + j) * R + by + tx] = tile[tx][ty + j];
}

// ---------------- packed f32x2 helpers ----------------------------------------
__device__ __forceinline__ ull dup2(float x) {
    ull r; asm("mov.b64 %0, {%1, %1};" : "=l"(r) : "f"(x)); return r;
}
__device__ __forceinline__ void fma2(ull& d, ull a, ull b) {
    asm("fma.rn.f32x2 %0, %1, %2, %0;" : "+l"(d) : "l"(a), "l"(b));
}
__device__ __forceinline__ float2 unpk(ull v) {
    float2 f; asm("mov.b64 {%0, %1}, %2;" : "=f"(f.x), "=f"(f.y) : "l"(v)); return f;
}
__device__ __forceinline__ float ex2f(float x) {
    float r; asm("ex2.approx.f32 %0, %1;" : "=f"(r) : "f"(x)); return r;
}
__device__ __forceinline__ uint32_t smem_u32(const void* p) {
    uint32_t a;
    asm("{ .reg .u64 t; cvta.to.shared.u64 t, %1; cvt.u32.u64 %0, t; }" : "=r"(a) : "l"(p));
    return a;
}
__device__ __forceinline__ void cpa16(uint32_t dst, const void* src) {
    asm volatile("cp.async.ca.shared.global [%0], [%1], 16;" :: "r"(dst), "l"(src));
}
#define CPA_COMMIT() asm volatile("cp.async.commit_group;" ::: "memory")
#define CPA_WAIT1()  asm volatile("cp.async.wait_group 1;" ::: "memory")
#define CPA_WAIT0()  asm volatile("cp.async.wait_group 0;" ::: "memory")

// ---------------- cp.async f32x2 GEMM, 64x128 tiles, 128 threads ----------------
// C[M,N] = A[M,K] @ B[K,N], At = A^T ([K][M]). brow0 = row-block offset (in
// 64-row units) so the Wo GEMM can be launched per batch.
__global__ __launch_bounds__(128, 4)
void gemm_cpa_kernel(const float* __restrict__ At, const float* __restrict__ B,
                     float* __restrict__ C, int M, int N, int K,
                     float* sumsq, int do_sumsq, int brow0)
{
    __shared__ __align__(16) float As[3][16][64];
    __shared__ __align__(16) float Bs[3][16][128];
    __shared__ float red[128];

    const int tid  = threadIdx.x;
    const int bcol = blockIdx.x;
    const int brow = blockIdx.y + brow0;
    const int trow = (tid >> 4) * 8;
    const int tcol = (tid & 15) * 4;

    const float* Atb = At + brow * 64;
    const float* Bb  = B + bcol * 128;
    const int KT = K / 16;

    const uint32_t sA = smem_u32(As);
    const uint32_t sB = smem_u32(Bs);

    const int a_kr0 = tid >> 4;
    const int a_mo  = (tid & 15) * 4;
    const int b_kr0 = tid >> 5;
    const int b_no  = (tid & 31) * 4;

    auto issue_tile = [&](int kt, int slot) {
        const uint32_t sa = sA + (uint32_t)slot * 4096;
        const uint32_t sb = sB + (uint32_t)slot * 8192;
        cpa16(sa + (uint32_t)(a_kr0 * 256 + a_mo * 4),
              Atb + (size_t)(kt * 16 + a_kr0) * M + a_mo);
        cpa16(sa + (uint32_t)((a_kr0 + 8) * 256 + a_mo * 4),
              Atb + (size_t)(kt * 16 + a_kr0 + 8) * M + a_mo);
#pragma unroll
        for (int l = 0; l < 4; l++) {
            int kr = b_kr0 + l * 4;
            cpa16(sb + (uint32_t)(kr * 512 + b_no * 4),
                  Bb + (size_t)(kt * 16 + kr) * N + b_no);
        }
        CPA_COMMIT();
    };

    ull acc[4][8];
#pragma unroll
    for (int rp = 0; rp < 4; rp++)
#pragma unroll
        for (int j = 0; j < 8; j++) acc[rp][j] = 0ULL;

    issue_tile(0, 0);
    issue_tile(1, 1);

    for (int t = 0; t < KT; t++) {
        const int s = t % 3;
        CPA_WAIT1();
        __syncthreads();
        if (t + 2 < KT) issue_tile(t + 2, (t + 2) % 3);
        else            CPA_COMMIT();

#pragma unroll
        for (int kk = 0; kk < 16; kk++) {
            ulonglong2 a01 = *(const ulonglong2*)&As[s][kk][trow];
            ulonglong2 a23 = *(const ulonglong2*)&As[s][kk][trow + 4];
            float4 b0 = *(const float4*)&Bs[s][kk][tcol];
            float4 b1 = *(const float4*)&Bs[s][kk][tcol + 64];
            ull bd[8] = {dup2(b0.x), dup2(b0.y), dup2(b0.z), dup2(b0.w),
                         dup2(b1.x), dup2(b1.y), dup2(b1.z), dup2(b1.w)};
#pragma unroll
            for (int j = 0; j < 8; j++) {
                fma2(acc[0][j], a01.x, bd[j]);
                fma2(acc[1][j], a01.y, bd[j]);
                fma2(acc[2][j], a23.x, bd[j]);
                fma2(acc[3][j], a23.y, bd[j]);
            }
        }
    }

    const int colbase = bcol * 128;
    float ss = 0.0f;
#pragma unroll
    for (int rp = 0; rp < 4; rp++) {
        float2 u[8];
#pragma unroll
        for (int j = 0; j < 8; j++) u[j] = unpk(acc[rp][j]);
        const int rowa = brow * 64 + trow + 2 * rp;
        float4 a0 = {u[0].x, u[1].x, u[2].x, u[3].x};
        float4 a1 = {u[4].x, u[5].x, u[6].x, u[7].x};
        float4 b0 = {u[0].y, u[1].y, u[2].y, u[3].y};
        float4 b1 = {u[4].y, u[5].y, u[6].y, u[7].y};
        *(float4*)(C + (size_t)rowa * N + colbase + tcol)            = a0;
        *(float4*)(C + (size_t)rowa * N + colbase + tcol + 64)       = a1;
        *(float4*)(C + (size_t)(rowa + 1) * N + colbase + tcol)      = b0;
        *(float4*)(C + (size_t)(rowa + 1) * N + colbase + tcol + 64) = b1;
        if (do_sumsq && colbase < 2048)
            ss += a0.x*a0.x + a0.y*a0.y + a0.z*a0.z + a0.w*a0.w
                + a1.x*a1.x + a1.y*a1.y + a1.z*a1.z + a1.w*a1.w
                + b0.x*b0.x + b0.y*b0.y + b0.z*b0.z + b0.w*b0.w
                + b1.x*b1.x + b1.y*b1.y + b1.z*b1.z + b1.w*b1.w;
    }

    if (do_sumsq && colbase < 2048) {
        red[tid] = ss;
        __syncthreads();
        for (int s2 = 64; s2 > 0; s2 >>= 1) {
            if (tid < s2) red[tid] += red[tid + s2];
            __syncthreads();
        }
        if (tid == 0) atomicAdd(&sumsq[colbase < 1024 ? 0 : 1], red[0]);
    }
}

// ---------------- Flash attention (R11 config), per-batch launch ---------------
__global__ __launch_bounds__(128, 3)
void flash_kernel(const float* __restrict__ qkv, const float* __restrict__ inv,
                  const float* __restrict__ scale_q, const float* __restrict__ scale_k,
                  float* __restrict__ zt, int batch)
{
    extern __shared__ float sm[];
    float* Qst = sm;                    // [d][r] stride 68 (scaled, incl. LOG2E)
    float* Kst = Qst + 64 * 68;         // [d][c] stride 68 (raw)
    float* Vs  = Kst + 64 * 68;         // [c][d] stride 68 (raw, gmem layout)
    float* Pst = Vs  + 64 * 68;         // [j][r] stride 68

    const int tid = threadIdx.x;        // 0..127
    const int qt  = blockIdx.x;         // 0..15
    const int h   = blockIdx.y;
    const int b   = batch;
    const int trow = (tid >> 4) * 8;
    const int tcol = (tid & 15) * 4;

    const float wsc = inv[0] * inv[1] * LOG2E;
    const uint32_t vb = smem_u32(Vs);

    // ---- Q load (scaled): 64x64 ----
    {
        const int base = b * SEQ + qt * 64;
#pragma unroll
        for (int l = 0; l < 8; l++) {
            int idx = tid + l * 128;
            int r   = idx >> 4;
            int d   = (idx & 15) * 4;
            float4 v = *(const float4*)(qkv + (size_t)(base + r) * 3072 + h * DH + d);
            Qst[(d + 0) * 68 + r] = v.x * wsc * scale_q[d + 0] * scale_k[d + 0];
            Qst[(d + 1) * 68 + r] = v.y * wsc * scale_q[d + 1] * scale_k[d + 1];
            Qst[(d + 2) * 68 + r] = v.z * wsc * scale_q[d + 2] * scale_k[d + 2];
            Qst[(d + 3) * 68 + r] = v.w * wsc * scale_q[d + 3] * scale_k[d + 3];
        }
    }

    const int kc = tid >> 4;
    const int kd = (tid & 15) * 4;
    const int base_kv = b * SEQ;

    // ---- prologue: K(0) LDG->STS; sync; V(0) cp.async ----
#pragma unroll
    for (int u = 0; u < 8; u++) {
        int c = kc + u * 8;
        float4 kv = *(const float4*)(qkv + (size_t)(base_kv + c) * 3072 + 1024 + h * DH + kd);
        Kst[(kd + 0) * 68 + c] = kv.x;
        Kst[(kd + 1) * 68 + c] = kv.y;
        Kst[(kd + 2) * 68 + c] = kv.z;
        Kst[(kd + 3) * 68 + c] = kv.w;
    }
    __syncthreads();
#pragma unroll
    for (int u = 0; u < 8; u++) {
        int c = kc + u * 8;
        cpa16(vb + (uint32_t)(c * 68 + kd) * 4,
              qkv + (size_t)(base_kv + c) * 3072 + 2048 + h * DH + kd);
    }
    CPA_COMMIT();

    ull o2[4][4];
    float lp[8];
#pragma unroll
    for (int i = 0; i < 8; i++) lp[i] = 0.0f;
#pragma unroll
    for (int rp = 0; rp < 4; rp++)
#pragma unroll
        for (int c = 0; c < 4; c++) o2[rp][c] = 0ULL;

    for (int t = 0; t < 16; t++) {
        ull s2[4][4];
#pragma unroll
        for (int rp = 0; rp < 4; rp++)
#pragma unroll
            for (int c = 0; c < 4; c++) s2[rp][c] = 0ULL;

#pragma unroll 8
        for (int d = 0; d < 64; d++) {
            ulonglong2 q01 = *(const ulonglong2*)&Qst[d * 68 + trow];
            ulonglong2 q23 = *(const ulonglong2*)&Qst[d * 68 + trow + 4];
            float4 kv = *(const float4*)&Kst[d * 68 + tcol];
            ull kd4[4] = {dup2(kv.x), dup2(kv.y), dup2(kv.z), dup2(kv.w)};
#pragma unroll
            for (int c = 0; c < 4; c++) {
                fma2(s2[0][c], q01.x, kd4[c]);
                fma2(s2[1][c], q01.y, kd4[c]);
                fma2(s2[2][c], q23.x, kd4[c]);
                fma2(s2[3][c], q23.y, kd4[c]);
            }
        }

#pragma unroll
        for (int rp = 0; rp < 4; rp++) {
            float2 c0 = unpk(s2[rp][0]);
            float2 c1 = unpk(s2[rp][1]);
            float2 c2 = unpk(s2[rp][2]);
            float2 c3 = unpk(s2[rp][3]);
            float pa0 = ex2f(c0.x), pb0 = ex2f(c0.y);
            float pa1 = ex2f(c1.x), pb1 = ex2f(c1.y);
            float pa2 = ex2f(c2.x), pb2 = ex2f(c2.y);
            float pa3 = ex2f(c3.x), pb3 = ex2f(c3.y);

            *(float2*)&Pst[(tcol + 0) * 68 + trow + 2 * rp] = make_float2(pa0, pb0);
            *(float2*)&Pst[(tcol + 1) * 68 + trow + 2 * rp] = make_float2(pa1, pb1);
            *(float2*)&Pst[(tcol + 2) * 68 + trow + 2 * rp] = make_float2(pa2, pb2);
            *(float2*)&Pst[(tcol + 3) * 68 + trow + 2 * rp] = make_float2(pa3, pb3);

            lp[2 * rp]     += (pa0 + pa1) + (pa2 + pa3);
            lp[2 * rp + 1] += (pb0 + pb1) + (pb2 + pb3);
        }
        CPA_WAIT0();
        __syncthreads();

        const bool pref = (t + 1) < 16;
        float4 rk[8];
        if (pref) {
            const int srow = base_kv + (t + 1) * 64;
#pragma unroll
            for (int u = 0; u < 8; u++)
                rk[u] = *(const float4*)(qkv + (size_t)(srow + kc + u * 8) * 3072 + 1024 + h * DH + kd);
        }

#pragma unroll 8
        for (int j = 0; j < 32; j++) {
            ulonglong2 p01 = *(const ulonglong2*)&Pst[j * 68 + trow];
            ulonglong2 p23 = *(const ulonglong2*)&Pst[j * 68 + trow + 4];
            float4 vv = *(const float4*)&Vs[j * 68 + tcol];
            ull vd[4] = {dup2(vv.x), dup2(vv.y), dup2(vv.z), dup2(vv.w)};
#pragma unroll
            for (int c = 0; c < 4; c++) {
                fma2(o2[0][c], p01.x, vd[c]);
                fma2(o2[1][c], p01.y, vd[c]);
                fma2(o2[2][c], p23.x, vd[c]);
                fma2(o2[3][c], p23.y, vd[c]);
            }
        }

        if (pref) {
#pragma unroll
            for (int u = 0; u < 8; u++) {
                int c = kc + u * 8;
                Kst[(kd + 0) * 68 + c] = rk[u].x;
                Kst[(kd + 1) * 68 + c] = rk[u].y;
                Kst[(kd + 2) * 68 + c] = rk[u].z;
                Kst[(kd + 3) * 68 + c] = rk[u].w;
            }
        }

#pragma unroll 8
        for (int j = 32; j < 64; j++) {
            ulonglong2 p01 = *(const ulonglong2*)&Pst[j * 68 + trow];
            ulonglong2 p23 = *(const ulonglong2*)&Pst[j * 68 + trow + 4];
            float4 vv = *(const float4*)&Vs[j * 68 + tcol];
            ull vd[4] = {dup2(vv.x), dup2(vv.y), dup2(vv.z), dup2(vv.w)};
#pragma unroll
            for (int c = 0; c < 4; c++) {
                fma2(o2[0][c], p01.x, vd[c]);
                fma2(o2[1][c], p01.y, vd[c]);
                fma2(o2[2][c], p23.x, vd[c]);
                fma2(o2[3][c], p23.y, vd[c]);
            }
        }

        __syncthreads();
        if (pref) {
            const int srow = base_kv + (t + 1) * 64;
#pragma unroll
            for (int u = 0; u < 8; u++) {
                int c = kc + u * 8;
                cpa16(vb + (uint32_t)(c * 68 + kd) * 4,
                      qkv + (size_t)(srow + c) * 3072 + 2048 + h * DH + kd);
            }
            CPA_COMMIT();
        }
    }

#pragma unroll
    for (int i = 0; i < 8; i++) {
#pragma unroll
        for (int off = 8; off >= 1; off >>= 1)
            lp[i] += __shfl_xor_sync(0xffffffffu, lp[i], off);
    }

    {
        float rl[8];
#pragma unroll
        for (int i = 0; i < 8; i++) rl[i] = 1.0f / lp[i];
        const int colb = h * DH + tcol;
        const int rowb = b * SEQ + qt * 64 + trow;
        float2 u0, u1, u2, u3;
#pragma unroll
        for (int cc = 0; cc < 4; cc++) {
            u0 = unpk(o2[0][cc]); u1 = unpk(o2[1][cc]);
            u2 = unpk(o2[2][cc]); u3 = unpk(o2[3][cc]);
            float4 w0 = {u0.x * rl[0], u0.y * rl[1], u1.x * rl[2], u1.y * rl[3]};
            float4 w1 = {u2.x * rl[4], u2.y * rl[5], u3.x * rl[6], u3.y * rl[7]};
            *(float4*)(zt + (size_t)(colb + cc) * MROWS + rowb)     = w0;
            *(float4*)(zt + (size_t)(colb + cc) * MROWS + rowb + 4) = w1;
        }
    }
}

// ---------------- launcher: fork Wo(b) onto a second stream --------------------
extern "C" void kernel_launch(void* const* d_in, const int* in_sizes, int n_in,
                              void* d_out, int out_size)
{
    const float* x    = (const float*)d_in[0];
    const float* Wqkv = (const float*)d_in[1];
    const float* Wo   = (const float*)d_in[2];
    const float* sq   = (const float*)d_in[3];
    const float* sk   = (const float*)d_in[4];
    float* out = (float*)d_out;

    float *qkv, *xt, *zt, *ss, *inv;
    cudaGetSymbolAddress((void**)&qkv, g_qkv);
    cudaGetSymbolAddress((void**)&xt,  g_xt);
    cudaGetSymbolAddress((void**)&zt,  g_zt);
    cudaGetSymbolAddress((void**)&ss,  g_sumsq);
    cudaGetSymbolAddress((void**)&inv, g_inv);

    static cudaStream_t s1;
    static cudaEvent_t evF[BATCH], evJ;
    static bool init_done = false;
    if (!init_done) {
        cudaStreamCreateWithFlags(&s1, cudaStreamNonBlocking);
        for (int i = 0; i < BATCH; i++)
            cudaEventCreateWithFlags(&evF[i], cudaEventDisableTiming);
        cudaEventCreateWithFlags(&evJ, cudaEventDisableTiming);
        cudaFuncSetAttribute(flash_kernel, cudaFuncAttributeMaxDynamicSharedMemorySize, 69632);
        init_done = true;
    }

    // x^T (+ zero sumsq)
    transpose_kernel<<<dim3(D_MODEL / 32, MROWS / 32), 256>>>(x, xt, MROWS, D_MODEL, ss);

    // QKV GEMM (fused q/k sum-of-squares)
    gemm_cpa_kernel<<<dim3(3 * D_MODEL / 128, MROWS / 64), 128>>>(
        xt, Wqkv, qkv, MROWS, 3 * D_MODEL, D_MODEL, ss, 1, 0);

    finalize_kernel<<<1, 32>>>(ss, inv);

    // per-batch flash on the main stream; Wo(b) forked onto s1 behind evF[b]
    for (int b = 0; b < BATCH; b++) {
        flash_kernel<<<dim3(SEQ / 64, NH, 1), 128, 69632>>>(qkv, inv, sq, sk, zt, b);
        cudaEventRecord(evF[b], 0);
        cudaStreamWaitEvent(s1, evF[b], 0);
        gemm_cpa_kernel<<<dim3(D_MODEL / 128, SEQ / 64), 128, 0, s1>>>(
            zt, Wo, out, MROWS, D_MODEL, D_MODEL, nullptr, 0, b * (SEQ / 64));
    }

    // join s1 back into the main stream
    cudaEventRecord(evJ, s1);
    cudaStreamWaitEvent(0, evJ, 0);
}

// round 16
// speedup vs baseline: 1.2306x; 1.2306x over previous
#include <cuda_runtime.h>
#include <math.h>
#include <stdint.h>

#define D_MODEL 1024
#define NH 16
#define DH 64
#define BATCH 4
#define SEQ 1024
#define MROWS (BATCH*SEQ)        // 4096
#define QK_COUNT 4194304.0f
#define EPS 1e-6f
#define LOG2E 1.4426950408889634f

typedef unsigned long long ull;

// ---------------- scratch ---------------------------------------------------
__device__ float g_qkv[MROWS * 3 * D_MODEL];   // 48 MB
__device__ float g_xt[D_MODEL * MROWS];        // 16 MB  (x^T)
__device__ float g_zt[D_MODEL * MROWS];        // 16 MB  (z^T, written by flash)
__device__ float g_sumsq[2];
__device__ float g_inv[2];

// ---------------- tiny kernels ----------------------------------------------
__global__ void finalize_kernel(const float* __restrict__ ss, float* __restrict__ inv) {
    if (threadIdx.x < 2) {
        float rms = sqrtf(ss[threadIdx.x] / QK_COUNT);
        inv[threadIdx.x] = 1.0f / (rms + EPS);
    }
}

// ---------------- transpose (+ zero sumsq): out[C][R] = in[R][C] ---------------
__global__ __launch_bounds__(256)
void transpose_kernel(const float* __restrict__ in, float* __restrict__ out,
                      int R, int C, float* ss)
{
    __shared__ float tile[32][33];
    if (blockIdx.x == 0 && blockIdx.y == 0 && threadIdx.x < 2) ss[threadIdx.x] = 0.0f;
    const int tx = threadIdx.x & 31;
    const int ty = threadIdx.x >> 5;
    const int bx = blockIdx.x * 32;
    const int by = blockIdx.y * 32;
#pragma unroll
    for (int j = 0; j < 32; j += 8)
        tile[ty + j][tx] = in[(size_t)(by + ty + j) * C + bx + tx];
    __syncthreads();
#pragma unroll
    for (int j = 0; j < 32; j += 8)
        out[(size_t)(bx + ty + j) * R + by + tx] = tile[tx][ty + j];
}

// ---------------- packed f32x2 helpers ----------------------------------------
__device__ __forceinline__ ull dup2(float x) {
    ull r; asm("mov.b64 %0, {%1, %1};" : "=l"(r) : "f"(x)); return r;
}
__device__ __forceinline__ void fma2(ull& d, ull a, ull b) {
    asm("fma.rn.f32x2 %0, %1, %2, %0;" : "+l"(d) : "l"(a), "l"(b));
}
__device__ __forceinline__ float2 unpk(ull v) {
    float2 f; asm("mov.b64 {%0, %1}, %2;" : "=f"(f.x), "=f"(f.y) : "l"(v)); return f;
}
__device__ __forceinline__ float ex2f(float x) {
    float r; asm("ex2.approx.f32 %0, %1;" : "=f"(r) : "f"(x)); return r;
}
__device__ __forceinline__ uint32_t smem_u32(const void* p) {
    uint32_t a;
    asm("{ .reg .u64 t; cvta.to.shared.u64 t, %1; cvt.u32.u64 %0, t; }" : "=r"(a) : "l"(p));
    return a;
}
__device__ __forceinline__ void cpa16(uint32_t dst, const void* src) {
    asm volatile("cp.async.ca.shared.global [%0], [%1], 16;" :: "r"(dst), "l"(src));
}
#define CPA_COMMIT() asm volatile("cp.async.commit_group;" ::: "memory")
#define CPA_WAIT0()  asm volatile("cp.async.wait_group 0;" ::: "memory")

// ---------------- cp.async f32x2 GEMM, 64x128 tiles, BK=32, 2-stage ------------
// C[M,N] = A[M,K] @ B[K,N], At = A^T ([K][M]). Depth-1 prefetch; one wait +
// two syncs per 32-deep k-tile (half the barrier count of BK=16).
// Loader (FIXED): A stage = 512 chunks -> 4/thread; B stage = 1024 -> 8/thread.
__global__ __launch_bounds__(128, 4)
void gemm_cpa_kernel(const float* __restrict__ At, const float* __restrict__ B,
                     float* __restrict__ C, int M, int N, int K,
                     float* sumsq, int do_sumsq)
{
    __shared__ __align__(16) float As[2][32][64];    // 8 KB / stage
    __shared__ __align__(16) float Bs[2][32][128];   // 16 KB / stage
    __shared__ float red[128];

    const int tid  = threadIdx.x;       // 0..127
    const int bcol = blockIdx.x;
    const int brow = blockIdx.y;        // 64-row block
    const int trow = (tid >> 4) * 8;    // 0..56
    const int tcol = (tid & 15) * 4;    // 0..60

    const float* Atb = At + brow * 64;
    const float* Bb  = B + bcol * 128;
    const int KT = K / 32;

    const uint32_t sA = smem_u32(As);
    const uint32_t sB = smem_u32(Bs);

    // A: chunk c = tid + l*128 (l<4): kr = c>>4 (0..31), mo = (c&15)*4
    const int a_kr0 = tid >> 4;          // 0..7 (+8 per l)
    const int a_mo  = (tid & 15) * 4;    // 0..60
    // B: chunk c = tid + l*128 (l<8): kr = c>>5 (0..31), no = (c&31)*4
    const int b_kr0 = tid >> 5;          // 0..3 (+4 per l)
    const int b_no  = (tid & 31) * 4;    // 0..124

    auto issue_tile = [&](int kt, int slot) {
        const uint32_t sa = sA + (uint32_t)slot * 8192;
        const uint32_t sb = sB + (uint32_t)slot * 16384;
#pragma unroll
        for (int l = 0; l < 4; l++) {
            int kr = a_kr0 + l * 8;
            cpa16(sa + (uint32_t)(kr * 256 + a_mo * 4),
                  Atb + (size_t)(kt * 32 + kr) * M + a_mo);
        }
#pragma unroll
        for (int l = 0; l < 8; l++) {
            int kr = b_kr0 + l * 4;
            cpa16(sb + (uint32_t)(kr * 512 + b_no * 4),
                  Bb + (size_t)(kt * 32 + kr) * N + b_no);
        }
        CPA_COMMIT();
    };

    ull acc[4][8];
#pragma unroll
    for (int rp = 0; rp < 4; rp++)
#pragma unroll
        for (int j = 0; j < 8; j++) acc[rp][j] = 0ULL;

    issue_tile(0, 0);

    for (int t = 0; t < KT; t++) {
        const int s = t & 1;
        CPA_WAIT0();                 // all outstanding groups (tile t) landed
        __syncthreads();             // visible to all; stage s^1 free
        if (t + 1 < KT) issue_tile(t + 1, s ^ 1);

#pragma unroll 8
        for (int kk = 0; kk < 32; kk++) {
            ulonglong2 a01 = *(const ulonglong2*)&As[s][kk][trow];
            ulonglong2 a23 = *(const ulonglong2*)&As[s][kk][trow + 4];
            float4 b0 = *(const float4*)&Bs[s][kk][tcol];
            float4 b1 = *(const float4*)&Bs[s][kk][tcol + 64];
            ull bd[8] = {dup2(b0.x), dup2(b0.y), dup2(b0.z), dup2(b0.w),
                         dup2(b1.x), dup2(b1.y), dup2(b1.z), dup2(b1.w)};
#pragma unroll
            for (int j = 0; j < 8; j++) {
                fma2(acc[0][j], a01.x, bd[j]);
                fma2(acc[1][j], a01.y, bd[j]);
                fma2(acc[2][j], a23.x, bd[j]);
                fma2(acc[3][j], a23.y, bd[j]);
            }
        }
        __syncthreads();             // compute(t) done before stage s overwritten
    }

    const int colbase = bcol * 128;
    float ss = 0.0f;
#pragma unroll
    for (int rp = 0; rp < 4; rp++) {
        float2 u[8];
#pragma unroll
        for (int j = 0; j < 8; j++) u[j] = unpk(acc[rp][j]);
        const int rowa = brow * 64 + trow + 2 * rp;
        float4 a0 = {u[0].x, u[1].x, u[2].x, u[3].x};
        float4 a1 = {u[4].x, u[5].x, u[6].x, u[7].x};
        float4 b0 = {u[0].y, u[1].y, u[2].y, u[3].y};
        float4 b1 = {u[4].y, u[5].y, u[6].y, u[7].y};
        *(float4*)(C + (size_t)rowa * N + colbase + tcol)            = a0;
        *(float4*)(C + (size_t)rowa * N + colbase + tcol + 64)       = a1;
        *(float4*)(C + (size_t)(rowa + 1) * N + colbase + tcol)      = b0;
        *(float4*)(C + (size_t)(rowa + 1) * N + colbase + tcol + 64) = b1;
        if (do_sumsq && colbase < 2048)
            ss += a0.x*a0.x + a0.y*a0.y + a0.z*a0.z + a0.w*a0.w
                + a1.x*a1.x + a1.y*a1.y + a1.z*a1.z + a1.w*a1.w
                + b0.x*b0.x + b0.y*b0.y + b0.z*b0.z + b0.w*b0.w
                + b1.x*b1.x + b1.y*b1.y + b1.z*b1.z + b1.w*b1.w;
    }

    if (do_sumsq && colbase < 2048) {
        red[tid] = ss;
        __syncthreads();
        for (int s2 = 64; s2 > 0; s2 >>= 1) {
            if (tid < s2) red[tid] += red[tid + s2];
            __syncthreads();
        }
        if (tid == 0) atomicAdd(&sumsq[colbase < 1024 ? 0 : 1], red[0]);
    }
}

// ---------------- Flash attention (R13/R11 config, single launch) --------------
__global__ __launch_bounds__(128, 3)
void flash_kernel(const float* __restrict__ qkv, const float* __restrict__ inv,
                  const float* __restrict__ scale_q, const float* __restrict__ scale_k,
                  float* __restrict__ zt)
{
    extern __shared__ float sm[];
    float* Qst = sm;                    // [d][r] stride 68 (scaled, incl. LOG2E)
    float* Kst = Qst + 64 * 68;         // [d][c] stride 68 (raw)
    float* Vs  = Kst + 64 * 68;         // [c][d] stride 68 (raw, gmem layout)
    float* Pst = Vs  + 64 * 68;         // [j][r] stride 68

    const int tid = threadIdx.x;        // 0..127
    const int qt  = blockIdx.x;         // 0..15
    const int h   = blockIdx.y;
    const int b   = blockIdx.z;
    const int trow = (tid >> 4) * 8;
    const int tcol = (tid & 15) * 4;

    const float wsc = inv[0] * inv[1] * LOG2E;
    const uint32_t vb = smem_u32(Vs);

    // ---- Q load (scaled): 64x64 ----
    {
        const int base = b * SEQ + qt * 64;
#pragma unroll
        for (int l = 0; l < 8; l++) {
            int idx = tid + l * 128;
            int r   = idx >> 4;
            int d   = (idx & 15) * 4;
            float4 v = *(const float4*)(qkv + (size_t)(base + r) * 3072 + h * DH + d);
            Qst[(d + 0) * 68 + r] = v.x * wsc * scale_q[d + 0] * scale_k[d + 0];
            Qst[(d + 1) * 68 + r] = v.y * wsc * scale_q[d + 1] * scale_k[d + 1];
            Qst[(d + 2) * 68 + r] = v.z * wsc * scale_q[d + 2] * scale_k[d + 2];
            Qst[(d + 3) * 68 + r] = v.w * wsc * scale_q[d + 3] * scale_k[d + 3];
        }
    }

    const int kc = tid >> 4;
    const int kd = (tid & 15) * 4;
    const int base_kv = b * SEQ;

    // ---- prologue: K(0) LDG->STS; sync; V(0) cp.async ----
#pragma unroll
    for (int u = 0; u < 8; u++) {
        int c = kc + u * 8;
        float4 kv = *(const float4*)(qkv + (size_t)(base_kv + c) * 3072 + 1024 + h * DH + kd);
        Kst[(kd + 0) * 68 + c] = kv.x;
        Kst[(kd + 1) * 68 + c] = kv.y;
        Kst[(kd + 2) * 68 + c] = kv.z;
        Kst[(kd + 3) * 68 + c] = kv.w;
    }
    __syncthreads();
#pragma unroll
    for (int u = 0; u < 8; u++) {
        int c = kc + u * 8;
        cpa16(vb + (uint32_t)(c * 68 + kd) * 4,
              qkv + (size_t)(base_kv + c) * 3072 + 2048 + h * DH + kd);
    }
    CPA_COMMIT();

    ull o2[4][4];
    float lp[8];
#pragma unroll
    for (int i = 0; i < 8; i++) lp[i] = 0.0f;
#pragma unroll
    for (int rp = 0; rp < 4; rp++)
#pragma unroll
        for (int c = 0; c < 4; c++) o2[rp][c] = 0ULL;

    for (int t = 0; t < 16; t++) {
        ull s2[4][4];
#pragma unroll
        for (int rp = 0; rp < 4; rp++)
#pragma unroll
            for (int c = 0; c < 4; c++) s2[rp][c] = 0ULL;

#pragma unroll 8
        for (int d = 0; d < 64; d++) {
            ulonglong2 q01 = *(const ulonglong2*)&Qst[d * 68 + trow];
            ulonglong2 q23 = *(const ulonglong2*)&Qst[d * 68 + trow + 4];
            float4 kv = *(const float4*)&Kst[d * 68 + tcol];
            ull kd4[4] = {dup2(kv.x), dup2(kv.y), dup2(kv.z), dup2(kv.w)};
#pragma unroll
            for (int c = 0; c < 4; c++) {
                fma2(s2[0][c], q01.x, kd4[c]);
                fma2(s2[1][c], q01.y, kd4[c]);
                fma2(s2[2][c], q23.x, kd4[c]);
                fma2(s2[3][c], q23.y, kd4[c]);
            }
        }

#pragma unroll
        for (int rp = 0; rp < 4; rp++) {
            float2 c0 = unpk(s2[rp][0]);
            float2 c1 = unpk(s2[rp][1]);
            float2 c2 = unpk(s2[rp][2]);
            float2 c3 = unpk(s2[rp][3]);
            float pa0 = ex2f(c0.x), pb0 = ex2f(c0.y);
            float pa1 = ex2f(c1.x), pb1 = ex2f(c1.y);
            float pa2 = ex2f(c2.x), pb2 = ex2f(c2.y);
            float pa3 = ex2f(c3.x), pb3 = ex2f(c3.y);

            *(float2*)&Pst[(tcol + 0) * 68 + trow + 2 * rp] = make_float2(pa0, pb0);
            *(float2*)&Pst[(tcol + 1) * 68 + trow + 2 * rp] = make_float2(pa1, pb1);
            *(float2*)&Pst[(tcol + 2) * 68 + trow + 2 * rp] = make_float2(pa2, pb2);
            *(float2*)&Pst[(tcol + 3) * 68 + trow + 2 * rp] = make_float2(pa3, pb3);

            lp[2 * rp]     += (pa0 + pa1) + (pa2 + pa3);
            lp[2 * rp + 1] += (pb0 + pb1) + (pb2 + pb3);
        }
        CPA_WAIT0();
        __syncthreads();

        const bool pref = (t + 1) < 16;
        float4 rk[8];
        if (pref) {
            const int srow = base_kv + (t + 1) * 64;
#pragma unroll
            for (int u = 0; u < 8; u++)
                rk[u] = *(const float4*)(qkv + (size_t)(srow + kc + u * 8) * 3072 + 1024 + h * DH + kd);
        }

#pragma unroll 8
        for (int j = 0; j < 32; j++) {
            ulonglong2 p01 = *(const ulonglong2*)&Pst[j * 68 + trow];
            ulonglong2 p23 = *(const ulonglong2*)&Pst[j * 68 + trow + 4];
            float4 vv = *(const float4*)&Vs[j * 68 + tcol];
            ull vd[4] = {dup2(vv.x), dup2(vv.y), dup2(vv.z), dup2(vv.w)};
#pragma unroll
            for (int c = 0; c < 4; c++) {
                fma2(o2[0][c], p01.x, vd[c]);
                fma2(o2[1][c], p01.y, vd[c]);
                fma2(o2[2][c], p23.x, vd[c]);
                fma2(o2[3][c], p23.y, vd[c]);
            }
        }

        if (pref) {
#pragma unroll
            for (int u = 0; u < 8; u++) {
                int c = kc + u * 8;
                Kst[(kd + 0) * 68 + c] = rk[u].x;
                Kst[(kd + 1) * 68 + c] = rk[u].y;
                Kst[(kd + 2) * 68 + c] = rk[u].z;
                Kst[(kd + 3) * 68 + c] = rk[u].w;
            }
        }

#pragma unroll 8
        for (int j = 32; j < 64; j++) {
            ulonglong2 p01 = *(const ulonglong2*)&Pst[j * 68 + trow];
            ulonglong2 p23 = *(const ulonglong2*)&Pst[j * 68 + trow + 4];
            float4 vv = *(const float4*)&Vs[j * 68 + tcol];
            ull vd[4] = {dup2(vv.x), dup2(vv.y), dup2(vv.z), dup2(vv.w)};
#pragma unroll
            for (int c = 0; c < 4; c++) {
                fma2(o2[0][c], p01.x, vd[c]);
                fma2(o2[1][c], p01.y, vd[c]);
                fma2(o2[2][c], p23.x, vd[c]);
                fma2(o2[3][c], p23.y, vd[c]);
            }
        }

        __syncthreads();
        if (pref) {
            const int srow = base_kv + (t + 1) * 64;
#pragma unroll
            for (int u = 0; u < 8; u++) {
                int c = kc + u * 8;
                cpa16(vb + (uint32_t)(c * 68 + kd) * 4,
                      qkv + (size_t)(srow + c) * 3072 + 2048 + h * DH + kd);
            }
            CPA_COMMIT();
        }
    }

#pragma unroll
    for (int i = 0; i < 8; i++) {
#pragma unroll
        for (int off = 8; off >= 1; off >>= 1)
            lp[i] += __shfl_xor_sync(0xffffffffu, lp[i], off);
    }

    {
        float rl[8];
#pragma unroll
        for (int i = 0; i < 8; i++) rl[i] = 1.0f / lp[i];
        const int colb = h * DH + tcol;
        const int rowb = b * SEQ + qt * 64 + trow;
        float2 u0, u1, u2, u3;
#pragma unroll
        for (int cc = 0; cc < 4; cc++) {
            u0 = unpk(o2[0][cc]); u1 = unpk(o2[1][cc]);
            u2 = unpk(o2[2][cc]); u3 = unpk(o2[3][cc]);
            float4 w0 = {u0.x * rl[0], u0.y * rl[1], u1.x * rl[2], u1.y * rl[3]};
            float4 w1 = {u2.x * rl[4], u2.y * rl[5], u3.x * rl[6], u3.y * rl[7]};
            *(float4*)(zt + (size_t)(colb + cc) * MROWS + rowb)     = w0;
            *(float4*)(zt + (size_t)(colb + cc) * MROWS + rowb + 4) = w1;
        }
    }
}

// ---------------- launcher ------------------------------------------------------
extern "C" void kernel_launch(void* const* d_in, const int* in_sizes, int n_in,
                              void* d_out, int out_size)
{
    const float* x    = (const float*)d_in[0];
    const float* Wqkv = (const float*)d_in[1];
    const float* Wo   = (const float*)d_in[2];
    const float* sq   = (const float*)d_in[3];
    const float* sk   = (const float*)d_in[4];
    float* out = (float*)d_out;

    float *qkv, *xt, *zt, *ss, *inv;
    cudaGetSymbolAddress((void**)&qkv, g_qkv);
    cudaGetSymbolAddress((void**)&xt,  g_xt);
    cudaGetSymbolAddress((void**)&zt,  g_zt);
    cudaGetSymbolAddress((void**)&ss,  g_sumsq);
    cudaGetSymbolAddress((void**)&inv, g_inv);

    static bool attr_done = false;
    if (!attr_done) {
        cudaFuncSetAttribute(flash_kernel, cudaFuncAttributeMaxDynamicSharedMemorySize, 69632);
        attr_done = true;
    }

    // x^T (+ zero sumsq)
    transpose_kernel<<<dim3(D_MODEL / 32, MROWS / 32), 256>>>(x, xt, MROWS, D_MODEL, ss);

    // QKV GEMM (fused q/k sum-of-squares): 64x128 tiles, BK=32
    gemm_cpa_kernel<<<dim3(3 * D_MODEL / 128, MROWS / 64), 128>>>(
        xt, Wqkv, qkv, MROWS, 3 * D_MODEL, D_MODEL, ss, 1);

    finalize_kernel<<<1, 32>>>(ss, inv);

    // flash: 64-row q-tiles, single launch, writes z^T
    flash_kernel<<<dim3(SEQ / 64, NH, BATCH), 128, 69632>>>(qkv, inv, sq, sk, zt);

    // output GEMM reads z^T directly
    gemm_cpa_kernel<<<dim3(D_MODEL / 128, MROWS / 64), 128>>>(
        zt, Wo, out, MROWS, D_MODEL, D_MODEL, nullptr, 0);
}

// round 17
// speedup vs baseline: 1.2532x; 1.0183x over previous
#include <cuda_runtime.h>
#include <math.h>
#include <stdint.h>

#define D_MODEL 1024
#define NH 16
#define DH 64
#define BATCH 4
#define SEQ 1024
#define MROWS (BATCH*SEQ)        // 4096
#define QK_COUNT 4194304.0f
#define EPS 1e-6f
#define LOG2E 1.4426950408889634f

typedef unsigned long long ull;

// ---------------- scratch ---------------------------------------------------
__device__ float g_qkv[MROWS * 3 * D_MODEL];   // 48 MB
__device__ float g_xt[D_MODEL * MROWS];        // 16 MB  (x^T)
__device__ float g_zt[D_MODEL * MROWS];        // 16 MB  (z^T, written by flash)
__device__ float g_sumsq[2];

// ---------------- transpose (+ zero sumsq): out[C][R] = in[R][C] ---------------
__global__ __launch_bounds__(256)
void transpose_kernel(const float* __restrict__ in, float* __restrict__ out,
                      int R, int C, float* ss)
{
    __shared__ float tile[32][33];
    if (blockIdx.x == 0 && blockIdx.y == 0 && threadIdx.x < 2) ss[threadIdx.x] = 0.0f;
    const int tx = threadIdx.x & 31;
    const int ty = threadIdx.x >> 5;
    const int bx = blockIdx.x * 32;
    const int by = blockIdx.y * 32;
#pragma unroll
    for (int j = 0; j < 32; j += 8)
        tile[ty + j][tx] = in[(size_t)(by + ty + j) * C + bx + tx];
    __syncthreads();
#pragma unroll
    for (int j = 0; j < 32; j += 8)
        out[(size_t)(bx + ty + j) * R + by + tx] = tile[tx][ty + j];
}

// ---------------- packed f32x2 helpers ----------------------------------------
__device__ __forceinline__ ull dup2(float x) {
    ull r; asm("mov.b64 %0, {%1, %1};" : "=l"(r) : "f"(x)); return r;
}
__device__ __forceinline__ void fma2(ull& d, ull a, ull b) {
    asm("fma.rn.f32x2 %0, %1, %2, %0;" : "+l"(d) : "l"(a), "l"(b));
}
__device__ __forceinline__ float2 unpk(ull v) {
    float2 f; asm("mov.b64 {%0, %1}, %2;" : "=f"(f.x), "=f"(f.y) : "l"(v)); return f;
}
__device__ __forceinline__ float ex2f(float x) {
    float r; asm("ex2.approx.f32 %0, %1;" : "=f"(r) : "f"(x)); return r;
}
__device__ __forceinline__ uint32_t smem_u32(const void* p) {
    uint32_t a;
    asm("{ .reg .u64 t; cvta.to.shared.u64 t, %1; cvt.u32.u64 %0, t; }" : "=r"(a) : "l"(p));
    return a;
}
__device__ __forceinline__ void cpa16(uint32_t dst, const void* src) {
    asm volatile("cp.async.ca.shared.global [%0], [%1], 16;" :: "r"(dst), "l"(src));
}
#define CPA_COMMIT() asm volatile("cp.async.commit_group;" ::: "memory")
#define CPA_WAIT1()  asm volatile("cp.async.wait_group 1;" ::: "memory")
#define CPA_WAIT0()  asm volatile("cp.async.wait_group 0;" ::: "memory")

// ---------------- cp.async f32x2 GEMM, 64x128 tiles, BK=16, 3-stage (R13) ------
__global__ __launch_bounds__(128, 4)
void gemm_cpa_kernel(const float* __restrict__ At, const float* __restrict__ B,
                     float* __restrict__ C, int M, int N, int K,
                     float* sumsq, int do_sumsq)
{
    __shared__ __align__(16) float As[3][16][64];    // 4 KB / stage
    __shared__ __align__(16) float Bs[3][16][128];   // 8 KB / stage
    __shared__ float red[128];

    const int tid  = threadIdx.x;       // 0..127
    const int bcol = blockIdx.x;
    const int brow = blockIdx.y;        // 64-row block
    const int trow = (tid >> 4) * 8;    // 0..56
    const int tcol = (tid & 15) * 4;    // 0..60

    const float* Atb = At + brow * 64;
    const float* Bb  = B + bcol * 128;
    const int KT = K / 16;

    const uint32_t sA = smem_u32(As);
    const uint32_t sB = smem_u32(Bs);

    // A tile: 256 16B-chunks -> 2/thread. chunk c: kr=c>>4, mo=(c&15)*4
    const int a_kr0 = tid >> 4;           // 0..7
    const int a_mo  = (tid & 15) * 4;
    // B tile: 512 chunks -> 4/thread. chunk c=tid+l*128: kr=c>>5, no=(c&31)*4
    const int b_kr0 = tid >> 5;           // 0..3 (+4 per l)
    const int b_no  = (tid & 31) * 4;

    auto issue_tile = [&](int kt, int slot) {
        const uint32_t sa = sA + (uint32_t)slot * 4096;
        const uint32_t sb = sB + (uint32_t)slot * 8192;
        cpa16(sa + (uint32_t)(a_kr0 * 256 + a_mo * 4),
              Atb + (size_t)(kt * 16 + a_kr0) * M + a_mo);
        cpa16(sa + (uint32_t)((a_kr0 + 8) * 256 + a_mo * 4),
              Atb + (size_t)(kt * 16 + a_kr0 + 8) * M + a_mo);
#pragma unroll
        for (int l = 0; l < 4; l++) {
            int kr = b_kr0 + l * 4;
            cpa16(sb + (uint32_t)(kr * 512 + b_no * 4),
                  Bb + (size_t)(kt * 16 + kr) * N + b_no);
        }
        CPA_COMMIT();
    };

    ull acc[4][8];
#pragma unroll
    for (int rp = 0; rp < 4; rp++)
#pragma unroll
        for (int j = 0; j < 8; j++) acc[rp][j] = 0ULL;

    issue_tile(0, 0);
    issue_tile(1, 1);

    for (int t = 0; t < KT; t++) {
        const int s = t % 3;
        CPA_WAIT1();
        __syncthreads();
        if (t + 2 < KT) issue_tile(t + 2, (t + 2) % 3);
        else            CPA_COMMIT();          // empty group keeps wait count uniform

#pragma unroll
        for (int kk = 0; kk < 16; kk++) {
            ulonglong2 a01 = *(const ulonglong2*)&As[s][kk][trow];
            ulonglong2 a23 = *(const ulonglong2*)&As[s][kk][trow + 4];
            float4 b0 = *(const float4*)&Bs[s][kk][tcol];
            float4 b1 = *(const float4*)&Bs[s][kk][tcol + 64];
            ull bd[8] = {dup2(b0.x), dup2(b0.y), dup2(b0.z), dup2(b0.w),
                         dup2(b1.x), dup2(b1.y), dup2(b1.z), dup2(b1.w)};
#pragma unroll
            for (int j = 0; j < 8; j++) {
                fma2(acc[0][j], a01.x, bd[j]);
                fma2(acc[1][j], a01.y, bd[j]);
                fma2(acc[2][j], a23.x, bd[j]);
                fma2(acc[3][j], a23.y, bd[j]);
            }
        }
    }

    const int colbase = bcol * 128;
    float ss = 0.0f;
#pragma unroll
    for (int rp = 0; rp < 4; rp++) {
        float2 u[8];
#pragma unroll
        for (int j = 0; j < 8; j++) u[j] = unpk(acc[rp][j]);
        const int rowa = brow * 64 + trow + 2 * rp;
        float4 a0 = {u[0].x, u[1].x, u[2].x, u[3].x};
        float4 a1 = {u[4].x, u[5].x, u[6].x, u[7].x};
        float4 b0 = {u[0].y, u[1].y, u[2].y, u[3].y};
        float4 b1 = {u[4].y, u[5].y, u[6].y, u[7].y};
        *(float4*)(C + (size_t)rowa * N + colbase + tcol)            = a0;
        *(float4*)(C + (size_t)rowa * N + colbase + tcol + 64)       = a1;
        *(float4*)(C + (size_t)(rowa + 1) * N + colbase + tcol)      = b0;
        *(float4*)(C + (size_t)(rowa + 1) * N + colbase + tcol + 64) = b1;
        if (do_sumsq && colbase < 2048)
            ss += a0.x*a0.x + a0.y*a0.y + a0.z*a0.z + a0.w*a0.w
                + a1.x*a1.x + a1.y*a1.y + a1.z*a1.z + a1.w*a1.w
                + b0.x*b0.x + b0.y*b0.y + b0.z*b0.z + b0.w*b0.w
                + b1.x*b1.x + b1.y*b1.y + b1.z*b1.z + b1.w*b1.w;
    }

    if (do_sumsq && colbase < 2048) {
        red[tid] = ss;
        __syncthreads();
        for (int s2 = 64; s2 > 0; s2 >>= 1) {
            if (tid < s2) red[tid] += red[tid + s2];
            __syncthreads();
        }
        if (tid == 0) atomicAdd(&sumsq[colbase < 1024 ? 0 : 1], red[0]);
    }
}

// ---------------- Flash attention (R13 config; inv computed inline) ------------
__global__ __launch_bounds__(128, 3)
void flash_kernel(const float* __restrict__ qkv, const float* __restrict__ ssq,
                  const float* __restrict__ scale_q, const float* __restrict__ scale_k,
                  float* __restrict__ zt)
{
    extern __shared__ float sm[];
    float* Qst = sm;                    // [d][r] stride 68 (scaled, incl. LOG2E)
    float* Kst = Qst + 64 * 68;         // [d][c] stride 68 (raw)
    float* Vs  = Kst + 64 * 68;         // [c][d] stride 68 (raw, gmem layout)
    float* Pst = Vs  + 64 * 68;         // [j][r] stride 68

    const int tid = threadIdx.x;        // 0..127
    const int qt  = blockIdx.x;         // 0..15
    const int h   = blockIdx.y;
    const int b   = blockIdx.z;
    const int trow = (tid >> 4) * 8;
    const int tcol = (tid & 15) * 4;

    // inline RMS normalizers (was finalize_kernel)
    const float inv0 = 1.0f / (sqrtf(ssq[0] / QK_COUNT) + EPS);
    const float inv1 = 1.0f / (sqrtf(ssq[1] / QK_COUNT) + EPS);
    const float wsc = inv0 * inv1 * LOG2E;
    const uint32_t vb = smem_u32(Vs);

    // ---- Q load (scaled): 64x64 ----
    {
        const int base = b * SEQ + qt * 64;
#pragma unroll
        for (int l = 0; l < 8; l++) {
            int idx = tid + l * 128;
            int r   = idx >> 4;
            int d   = (idx & 15) * 4;
            float4 v = *(const float4*)(qkv + (size_t)(base + r) * 3072 + h * DH + d);
            Qst[(d + 0) * 68 + r] = v.x * wsc * scale_q[d + 0] * scale_k[d + 0];
            Qst[(d + 1) * 68 + r] = v.y * wsc * scale_q[d + 1] * scale_k[d + 1];
            Qst[(d + 2) * 68 + r] = v.z * wsc * scale_q[d + 2] * scale_k[d + 2];
            Qst[(d + 3) * 68 + r] = v.w * wsc * scale_q[d + 3] * scale_k[d + 3];
        }
    }

    const int kc = tid >> 4;
    const int kd = (tid & 15) * 4;
    const int base_kv = b * SEQ;

    // ---- prologue: K(0) LDG->STS; sync; V(0) cp.async ----
#pragma unroll
    for (int u = 0; u < 8; u++) {
        int c = kc + u * 8;
        float4 kv = *(const float4*)(qkv + (size_t)(base_kv + c) * 3072 + 1024 + h * DH + kd);
        Kst[(kd + 0) * 68 + c] = kv.x;
        Kst[(kd + 1) * 68 + c] = kv.y;
        Kst[(kd + 2) * 68 + c] = kv.z;
        Kst[(kd + 3) * 68 + c] = kv.w;
    }
    __syncthreads();
#pragma unroll
    for (int u = 0; u < 8; u++) {
        int c = kc + u * 8;
        cpa16(vb + (uint32_t)(c * 68 + kd) * 4,
              qkv + (size_t)(base_kv + c) * 3072 + 2048 + h * DH + kd);
    }
    CPA_COMMIT();

    ull o2[4][4];
    float lp[8];
#pragma unroll
    for (int i = 0; i < 8; i++) lp[i] = 0.0f;
#pragma unroll
    for (int rp = 0; rp < 4; rp++)
#pragma unroll
        for (int c = 0; c < 4; c++) o2[rp][c] = 0ULL;

    for (int t = 0; t < 16; t++) {
        ull s2[4][4];
#pragma unroll
        for (int rp = 0; rp < 4; rp++)
#pragma unroll
            for (int c = 0; c < 4; c++) s2[rp][c] = 0ULL;

#pragma unroll 8
        for (int d = 0; d < 64; d++) {
            ulonglong2 q01 = *(const ulonglong2*)&Qst[d * 68 + trow];
            ulonglong2 q23 = *(const ulonglong2*)&Qst[d * 68 + trow + 4];
            float4 kv = *(const float4*)&Kst[d * 68 + tcol];
            ull kd4[4] = {dup2(kv.x), dup2(kv.y), dup2(kv.z), dup2(kv.w)};
#pragma unroll
            for (int c = 0; c < 4; c++) {
                fma2(s2[0][c], q01.x, kd4[c]);
                fma2(s2[1][c], q01.y, kd4[c]);
                fma2(s2[2][c], q23.x, kd4[c]);
                fma2(s2[3][c], q23.y, kd4[c]);
            }
        }

#pragma unroll
        for (int rp = 0; rp < 4; rp++) {
            float2 c0 = unpk(s2[rp][0]);
            float2 c1 = unpk(s2[rp][1]);
            float2 c2 = unpk(s2[rp][2]);
            float2 c3 = unpk(s2[rp][3]);
            float pa0 = ex2f(c0.x), pb0 = ex2f(c0.y);
            float pa1 = ex2f(c1.x), pb1 = ex2f(c1.y);
            float pa2 = ex2f(c2.x), pb2 = ex2f(c2.y);
            float pa3 = ex2f(c3.x), pb3 = ex2f(c3.y);

            *(float2*)&Pst[(tcol + 0) * 68 + trow + 2 * rp] = make_float2(pa0, pb0);
            *(float2*)&Pst[(tcol + 1) * 68 + trow + 2 * rp] = make_float2(pa1, pb1);
            *(float2*)&Pst[(tcol + 2) * 68 + trow + 2 * rp] = make_float2(pa2, pb2);
            *(float2*)&Pst[(tcol + 3) * 68 + trow + 2 * rp] = make_float2(pa3, pb3);

            lp[2 * rp]     += (pa0 + pa1) + (pa2 + pa3);
            lp[2 * rp + 1] += (pb0 + pb1) + (pb2 + pb3);
        }
        CPA_WAIT0();
        __syncthreads();

        const bool pref = (t + 1) < 16;
        float4 rk[8];
        if (pref) {
            const int srow = base_kv + (t + 1) * 64;
#pragma unroll
            for (int u = 0; u < 8; u++)
                rk[u] = *(const float4*)(qkv + (size_t)(srow + kc + u * 8) * 3072 + 1024 + h * DH + kd);
        }

#pragma unroll 8
        for (int j = 0; j < 32; j++) {
            ulonglong2 p01 = *(const ulonglong2*)&Pst[j * 68 + trow];
            ulonglong2 p23 = *(const ulonglong2*)&Pst[j * 68 + trow + 4];
            float4 vv = *(const float4*)&Vs[j * 68 + tcol];
            ull vd[4] = {dup2(vv.x), dup2(vv.y), dup2(vv.z), dup2(vv.w)};
#pragma unroll
            for (int c = 0; c < 4; c++) {
                fma2(o2[0][c], p01.x, vd[c]);
                fma2(o2[1][c], p01.y, vd[c]);
                fma2(o2[2][c], p23.x, vd[c]);
                fma2(o2[3][c], p23.y, vd[c]);
            }
        }

        if (pref) {
#pragma unroll
            for (int u = 0; u < 8; u++) {
                int c = kc + u * 8;
                Kst[(kd + 0) * 68 + c] = rk[u].x;
                Kst[(kd + 1) * 68 + c] = rk[u].y;
                Kst[(kd + 2) * 68 + c] = rk[u].z;
                Kst[(kd + 3) * 68 + c] = rk[u].w;
            }
        }

#pragma unroll 8
        for (int j = 32; j < 64; j++) {
            ulonglong2 p01 = *(const ulonglong2*)&Pst[j * 68 + trow];
            ulonglong2 p23 = *(const ulonglong2*)&Pst[j * 68 + trow + 4];
            float4 vv = *(const float4*)&Vs[j * 68 + tcol];
            ull vd[4] = {dup2(vv.x), dup2(vv.y), dup2(vv.z), dup2(vv.w)};
#pragma unroll
            for (int c = 0; c < 4; c++) {
                fma2(o2[0][c], p01.x, vd[c]);
                fma2(o2[1][c], p01.y, vd[c]);
                fma2(o2[2][c], p23.x, vd[c]);
                fma2(o2[3][c], p23.y, vd[c]);
            }
        }

        __syncthreads();
        if (pref) {
            const int srow = base_kv + (t + 1) * 64;
#pragma unroll
            for (int u = 0; u < 8; u++) {
                int c = kc + u * 8;
                cpa16(vb + (uint32_t)(c * 68 + kd) * 4,
                      qkv + (size_t)(srow + c) * 3072 + 2048 + h * DH + kd);
            }
            CPA_COMMIT();
        }
    }

#pragma unroll
    for (int i = 0; i < 8; i++) {
#pragma unroll
        for (int off = 8; off >= 1; off >>= 1)
            lp[i] += __shfl_xor_sync(0xffffffffu, lp[i], off);
    }

    {
        float rl[8];
#pragma unroll
        for (int i = 0; i < 8; i++) rl[i] = 1.0f / lp[i];
        const int colb = h * DH + tcol;
        const int rowb = b * SEQ + qt * 64 + trow;
        float2 u0, u1, u2, u3;
#pragma unroll
        for (int cc = 0; cc < 4; cc++) {
            u0 = unpk(o2[0][cc]); u1 = unpk(o2[1][cc]);
            u2 = unpk(o2[2][cc]); u3 = unpk(o2[3][cc]);
            float4 w0 = {u0.x * rl[0], u0.y * rl[1], u1.x * rl[2], u1.y * rl[3]};
            float4 w1 = {u2.x * rl[4], u2.y * rl[5], u3.x * rl[6], u3.y * rl[7]};
            *(float4*)(zt + (size_t)(colb + cc) * MROWS + rowb)     = w0;
            *(float4*)(zt + (size_t)(colb + cc) * MROWS + rowb + 4) = w1;
        }
    }
}

// ---------------- launcher ------------------------------------------------------
extern "C" void kernel_launch(void* const* d_in, const int* in_sizes, int n_in,
                              void* d_out, int out_size)
{
    const float* x    = (const float*)d_in[0];
    const float* Wqkv = (const float*)d_in[1];
    const float* Wo   = (const float*)d_in[2];
    const float* sq   = (const float*)d_in[3];
    const float* sk   = (const float*)d_in[4];
    float* out = (float*)d_out;

    float *qkv, *xt, *zt, *ss;
    cudaGetSymbolAddress((void**)&qkv, g_qkv);
    cudaGetSymbolAddress((void**)&xt,  g_xt);
    cudaGetSymbolAddress((void**)&zt,  g_zt);
    cudaGetSymbolAddress((void**)&ss,  g_sumsq);

    static bool attr_done = false;
    if (!attr_done) {
        cudaFuncSetAttribute(flash_kernel, cudaFuncAttributeMaxDynamicSharedMemorySize, 69632);
        attr_done = true;
    }

    // x^T (+ zero sumsq)
    transpose_kernel<<<dim3(D_MODEL / 32, MROWS / 32), 256>>>(x, xt, MROWS, D_MODEL, ss);

    // QKV GEMM (fused q/k sum-of-squares): 64x128 tiles, BK=16
    gemm_cpa_kernel<<<dim3(3 * D_MODEL / 128, MROWS / 64), 128>>>(
        xt, Wqkv, qkv, MROWS, 3 * D_MODEL, D_MODEL, ss, 1);

    // flash: inv computed inline from sumsq; writes z^T
    flash_kernel<<<dim3(SEQ / 64, NH, BATCH), 128, 69632>>>(qkv, ss, sq, sk, zt);

    // output GEMM reads z^T directly
    gemm_cpa_kernel<<<dim3(D_MODEL / 128, MROWS / 64), 128>>>(
        zt, Wo, out, MROWS, D_MODEL, D_MODEL, nullptr, 0);
}